// round 1
// baseline (speedup 1.0000x reference)
#include <cuda_runtime.h>
#include <cuda_bf16.h>

// Problem constants (fixed by the dataset)
#define NN 10000      // nodes
#define DD 256        // feature dim
#define HH 512        // hidden
#define EE 320000     // edges

// Scratch (device globals: allocation-free rule)
__device__ float4 g_agg[NN * (DD / 4)];   // [N, 256]  aggregated messages
__device__ float4 g_h  [NN * (HH / 4)];   // [N, 512]  relu(cat @ W_conv + b)

// ---------------------------------------------------------------------------
// zero agg
__global__ void k_zero_agg() {
    int i = blockIdx.x * blockDim.x + threadIdx.x;
    if (i < NN * (DD / 4)) g_agg[i] = make_float4(0.f, 0.f, 0.f, 0.f);
}

// out[n] = b2[0]  (bias pre-seeded; GEMM2 epilogue atomically accumulates)
__global__ void k_init_out(float* __restrict__ out, const float* __restrict__ b2) {
    int i = blockIdx.x * blockDim.x + threadIdx.x;
    if (i < NN) out[i] = b2[0];
}

// ---------------------------------------------------------------------------
// SpMM scatter: agg[dst] += x[src] * val   (one warp per edge, float4 atomics)
__global__ void k_scatter(const float4* __restrict__ x4,
                          const int*    __restrict__ esrc,
                          const int*    __restrict__ edst,
                          const float*  __restrict__ eval) {
    int gid  = blockIdx.x * blockDim.x + threadIdx.x;
    int w    = gid >> 5;
    int lane = gid & 31;
    if (w >= EE) return;
    int   s = __ldg(esrc + w);
    int   d = __ldg(edst + w);
    float v = __ldg(eval + w);
    const float4* xr = x4   + (size_t)s * (DD / 4);
    float4*       ar = g_agg + (size_t)d * (DD / 4);
    #pragma unroll
    for (int j = 0; j < 2; j++) {
        int c = lane + j * 32;              // 64 float4 per row
        float4 t = __ldg(xr + c);
        t.x *= v; t.y *= v; t.z *= v; t.w *= v;
        atomicAdd(ar + c, t);               // sm_90+ vector red.global
    }
}

// ---------------------------------------------------------------------------
// Tiled fp32 GEMM building blocks: 64x64 tile, BK=16, 256 threads, 4x4/thread
#define BM 64
#define BN 64
#define BK 16

// GEMM1: h = relu( [x | agg] @ W_conv + b_conv )    A:[N,512] B:[512,512]
__global__ __launch_bounds__(256)
void k_gemm1(const float* __restrict__ x,
             const float* __restrict__ Wc,
             const float* __restrict__ bc) {
    __shared__ float As[BK][BM];
    __shared__ float Bs[BK][BN];

    const int tx = threadIdx.x & 15;
    const int ty = threadIdx.x >> 4;
    const int rowBase = blockIdx.y * BM;
    const int colBase = blockIdx.x * BN;

    // load mappings
    const int la_row = threadIdx.x >> 2;         // 0..63
    const int la_kc  = (threadIdx.x & 3) * 4;    // 0,4,8,12
    const int lb_k   = threadIdx.x >> 4;         // 0..15
    const int lb_nc  = (threadIdx.x & 15) * 4;   // 0..60

    const float* aggf = (const float*)g_agg;

    float acc[4][4] = {};

    for (int kt = 0; kt < 2 * DD; kt += BK) {
        // --- A tile: columns <256 from x, >=256 from agg (BK divides 256)
        const float* Asrc = (kt < DD) ? x : aggf;
        const int kk0 = kt & (DD - 1);
        const int gr = rowBase + la_row;
        float4 a4 = make_float4(0.f, 0.f, 0.f, 0.f);
        if (gr < NN)
            a4 = *(const float4*)(Asrc + (size_t)gr * DD + kk0 + la_kc);
        As[la_kc + 0][la_row] = a4.x;
        As[la_kc + 1][la_row] = a4.y;
        As[la_kc + 2][la_row] = a4.z;
        As[la_kc + 3][la_row] = a4.w;
        // --- B tile (always in range)
        float4 b4 = *(const float4*)(Wc + (size_t)(kt + lb_k) * HH + colBase + lb_nc);
        *(float4*)&Bs[lb_k][lb_nc] = b4;
        __syncthreads();

        #pragma unroll
        for (int kk = 0; kk < BK; kk++) {
            float4 av = *(const float4*)&As[kk][ty * 4];
            float4 bv = *(const float4*)&Bs[kk][tx * 4];
            float a[4] = {av.x, av.y, av.z, av.w};
            float b[4] = {bv.x, bv.y, bv.z, bv.w};
            #pragma unroll
            for (int i = 0; i < 4; i++)
                #pragma unroll
                for (int j = 0; j < 4; j++)
                    acc[i][j] = fmaf(a[i], b[j], acc[i][j]);
        }
        __syncthreads();
    }

    // epilogue: + bias, relu, store h
    float* hf = (float*)g_h;
    const float4 bias = *(const float4*)(bc + colBase + tx * 4);
    #pragma unroll
    for (int i = 0; i < 4; i++) {
        int r = rowBase + ty * 4 + i;
        if (r < NN) {
            float4 o;
            o.x = fmaxf(acc[i][0] + bias.x, 0.f);
            o.y = fmaxf(acc[i][1] + bias.y, 0.f);
            o.z = fmaxf(acc[i][2] + bias.z, 0.f);
            o.w = fmaxf(acc[i][3] + bias.w, 0.f);
            *(float4*)(hf + (size_t)r * HH + colBase + tx * 4) = o;
        }
    }
}

// GEMM2 (fused head): z = prelu(h @ W1 + b1); out[r] += sum_c z[r,c]*W2[c]
__global__ __launch_bounds__(256)
void k_gemm2(const float* __restrict__ W1,
             const float* __restrict__ b1,
             const float* __restrict__ pa,
             const float* __restrict__ W2,
             float* __restrict__ out) {
    __shared__ float As[BK][BM];
    __shared__ float Bs[BK][BN];

    const int tx = threadIdx.x & 15;
    const int ty = threadIdx.x >> 4;
    const int rowBase = blockIdx.y * BM;
    const int colBase = blockIdx.x * BN;

    const int la_row = threadIdx.x >> 2;
    const int la_kc  = (threadIdx.x & 3) * 4;
    const int lb_k   = threadIdx.x >> 4;
    const int lb_nc  = (threadIdx.x & 15) * 4;

    const float* hf = (const float*)g_h;

    float acc[4][4] = {};

    for (int kt = 0; kt < HH; kt += BK) {
        const int gr = rowBase + la_row;
        float4 a4 = make_float4(0.f, 0.f, 0.f, 0.f);
        if (gr < NN)
            a4 = *(const float4*)(hf + (size_t)gr * HH + kt + la_kc);
        As[la_kc + 0][la_row] = a4.x;
        As[la_kc + 1][la_row] = a4.y;
        As[la_kc + 2][la_row] = a4.z;
        As[la_kc + 3][la_row] = a4.w;
        float4 b4 = *(const float4*)(W1 + (size_t)(kt + lb_k) * HH + colBase + lb_nc);
        *(float4*)&Bs[lb_k][lb_nc] = b4;
        __syncthreads();

        #pragma unroll
        for (int kk = 0; kk < BK; kk++) {
            float4 av = *(const float4*)&As[kk][ty * 4];
            float4 bv = *(const float4*)&Bs[kk][tx * 4];
            float a[4] = {av.x, av.y, av.z, av.w};
            float b[4] = {bv.x, bv.y, bv.z, bv.w};
            #pragma unroll
            for (int i = 0; i < 4; i++)
                #pragma unroll
                for (int j = 0; j < 4; j++)
                    acc[i][j] = fmaf(a[i], b[j], acc[i][j]);
        }
        __syncthreads();
    }

    // epilogue: bias, PReLU, dot with W2, reduce across 16 col-threads, atomic
    const int c0 = colBase + tx * 4;
    const float4 b1v = *(const float4*)(b1 + c0);
    const float4 pav = *(const float4*)(pa + c0);
    const float4 w2v = *(const float4*)(W2 + c0);   // W2 is [512,1] contiguous

    #pragma unroll
    for (int i = 0; i < 4; i++) {
        float z0 = acc[i][0] + b1v.x; z0 = z0 > 0.f ? z0 : pav.x * z0;
        float z1 = acc[i][1] + b1v.y; z1 = z1 > 0.f ? z1 : pav.y * z1;
        float z2 = acc[i][2] + b1v.z; z2 = z2 > 0.f ? z2 : pav.z * z2;
        float z3 = acc[i][3] + b1v.w; z3 = z3 > 0.f ? z3 : pav.w * z3;
        float local = fmaf(z0, w2v.x, fmaf(z1, w2v.y, fmaf(z2, w2v.z, z3 * w2v.w)));
        // reduce across tx (16-lane groups aligned within the warp)
        #pragma unroll
        for (int m = 8; m > 0; m >>= 1)
            local += __shfl_xor_sync(0xffffffffu, local, m);
        if (tx == 0) {
            int r = rowBase + ty * 4 + i;
            if (r < NN) atomicAdd(out + r, local);
        }
    }
}

// ---------------------------------------------------------------------------
extern "C" void kernel_launch(void* const* d_in, const int* in_sizes, int n_in,
                              void* d_out, int out_size) {
    const float* x     = (const float*)d_in[0];
    const int*   esrc  = (const int*)  d_in[1];
    const int*   edst  = (const int*)  d_in[2];
    const float* eval  = (const float*)d_in[3];
    const float* Wc    = (const float*)d_in[4];
    const float* bc    = (const float*)d_in[5];
    const float* W1    = (const float*)d_in[6];
    const float* b1    = (const float*)d_in[7];
    const float* pa    = (const float*)d_in[8];
    const float* W2    = (const float*)d_in[9];
    const float* b2    = (const float*)d_in[10];
    float* out = (float*)d_out;

    // 1) zero agg + seed out with b2
    k_zero_agg<<<(NN * (DD / 4) + 255) / 256, 256>>>();
    k_init_out<<<(NN + 255) / 256, 256>>>(out, b2);

    // 2) SpMM scatter (warp per edge)
    {
        long threads = (long)EE * 32;
        int blocks = (int)((threads + 255) / 256);
        k_scatter<<<blocks, 256>>>((const float4*)x, esrc, edst, eval);
    }

    // 3) GEMM1: h = relu([x|agg] @ W_conv + b_conv)
    {
        dim3 grid(HH / BN, (NN + BM - 1) / BM);
        k_gemm1<<<grid, 256>>>(x, Wc, bc);
    }

    // 4) GEMM2 fused with PReLU + W2 matvec head
    {
        dim3 grid(HH / BN, (NN + BM - 1) / BM);
        k_gemm2<<<grid, 256>>>(W1, b1, pa, W2, out);
    }
}